// round 1
// baseline (speedup 1.0000x reference)
#include <cuda_runtime.h>
#include <cstdint>

#define NN 16
#define WD 64
#define PITCH 33
#define TILE 32
#define NTHREADS 256
#define BUF_F (WD * PITCH)   // 2112 floats per [64][33] buffer

struct GraphDesc {
    unsigned pm[NN];     // predecessor bitmask per node
    unsigned sink_mask;  // nodes with no successors
};

// ---------------- device helpers ----------------

__device__ __forceinline__ unsigned long long pk2(float x) {
    unsigned long long r; unsigned xi = __float_as_uint(x);
    asm("mov.b64 %0, {%1, %1};" : "=l"(r) : "r"(xi));
    return r;
}
__device__ __forceinline__ unsigned long long pk2f(float lo, float hi) {
    unsigned long long r;
    asm("mov.b64 %0, {%1, %2};" : "=l"(r)
        : "r"(__float_as_uint(lo)), "r"(__float_as_uint(hi)));
    return r;
}
__device__ __forceinline__ void upk2(unsigned long long v, float& lo, float& hi) {
    unsigned a, b;
    asm("mov.b64 {%0, %1}, %2;" : "=r"(a), "=r"(b) : "l"(v));
    lo = __uint_as_float(a); hi = __uint_as_float(b);
}
// packed dual fp32 FMA (Blackwell FFMA2 via PTX fma.rn.f32x2)
__device__ __forceinline__ void ffma2(unsigned long long& acc,
                                      unsigned long long a, unsigned long long b) {
    asm("fma.rn.f32x2 %0, %1, %2, %0;" : "+l"(acc) : "l"(a), "l"(b));
}

// GRAPH_ACTS = [tanh, elu, softplus, sin, gaussian]
__device__ __forceinline__ float actf(int id, float v) {
    switch (id) {
        case 0:  return tanhf(v);
        case 1:  return v > 0.f ? v : expm1f(v);
        case 2:  return fmaxf(v, 0.f) + log1pf(expf(-fabsf(v)));
        case 3:  return sinf(v);
        default: return expf(-0.5f * v * v);
    }
}

// stage a 64x64 row-major global weight matrix into shared, transposed: w_sh[k*64+o]
__device__ __forceinline__ void stage_w(const float* __restrict__ gw,
                                        float* __restrict__ wsh, int t) {
    int o  = t >> 2;            // 0..63
    int kb = (t & 3) << 4;      // 0,16,32,48
    const float4* src = (const float4*)(gw + o * 64 + kb);
#pragma unroll
    for (int q = 0; q < 4; q++) {
        float4 v = src[q];
        int k = kb + q * 4;
        wsh[(k + 0) * 64 + o] = v.x;
        wsh[(k + 1) * 64 + o] = v.y;
        wsh[(k + 2) * 64 + o] = v.z;
        wsh[(k + 3) * 64 + o] = v.w;
    }
}

// out[s][o] = act( sum_k in[s][k] * W[o][k] + bias[o] )
// in/out column-major [64][PITCH]; wsh transposed [k][o]; thread = (s, og): 8 outputs
__device__ __forceinline__ void gemm64(const float* __restrict__ in,
                                       const float* __restrict__ wsh,
                                       const float* __restrict__ bias_g,
                                       int actId, float* __restrict__ out,
                                       int s, int og) {
    unsigned long long acc[4];
    const float2* bb = (const float2*)(bias_g + og * 8);
#pragma unroll
    for (int i = 0; i < 4; i++) { float2 b = bb[i]; acc[i] = pk2f(b.x, b.y); }

    const float* ap = in + s;
    const float* wp = wsh + og * 8;
#pragma unroll 8
    for (int k = 0; k < 64; k++) {
        unsigned long long a2 = pk2(ap[k * PITCH]);
        ulonglong2 w0 = *(const ulonglong2*)(wp + k * 64);
        ulonglong2 w1 = *(const ulonglong2*)(wp + k * 64 + 4);
        ffma2(acc[0], a2, w0.x);
        ffma2(acc[1], a2, w0.y);
        ffma2(acc[2], a2, w1.x);
        ffma2(acc[3], a2, w1.y);
    }
    float* op = out + og * 8 * PITCH + s;
#pragma unroll
    for (int i = 0; i < 4; i++) {
        float lo, hi; upk2(acc[i], lo, hi);
        op[(2 * i) * PITCH]     = actf(actId, lo);
        op[(2 * i + 1) * PITCH] = actf(actId, hi);
    }
}

// ---------------- kernel ----------------

__global__ void __launch_bounds__(NTHREADS, 1)
inr_kernel(const float* __restrict__ inp, const float* __restrict__ lats,
           const float* __restrict__ Wl, const float* __restrict__ bl,
           const float* __restrict__ Wx, const float* __restrict__ Wy,
           const float* __restrict__ Wr, const float* __restrict__ W1,
           const float* __restrict__ b1, const float* __restrict__ gW,
           const float* __restrict__ gB, const float* __restrict__ outW,
           const float* __restrict__ outb, const float* __restrict__ scale,
           float* __restrict__ out, GraphDesc gd) {
    extern __shared__ float sm[];
    float* w_sh  = sm;                 // 4096 floats
    float* in_sh = sm + 4096;          // BUF_F
    float* f_sh  = in_sh + BUF_F;      // BUF_F
    float* hs    = f_sh + BUF_F;       // 16 * BUF_F

    const int t  = threadIdx.x;
    const int s  = t & 31;
    const int og = t >> 5;
    const int gs = blockIdx.x * TILE + s;

    // ---- stage W1 while computing the encode into in_sh ----
    stage_w(W1, w_sh, t);
    {
        float xs = inp[gs * 3 + 0], ys = inp[gs * 3 + 1], rs = inp[gs * 3 + 2];
        float lat[8];
        const float4* lp = (const float4*)(lats + gs * 8);
        float4 l0 = lp[0], l1 = lp[1];
        lat[0] = l0.x; lat[1] = l0.y; lat[2] = l0.z; lat[3] = l0.w;
        lat[4] = l1.x; lat[5] = l1.y; lat[6] = l1.z; lat[7] = l1.w;
#pragma unroll
        for (int i = 0; i < 8; i++) {
            int o = og * 8 + i;
            float pre = bl[o];
#pragma unroll
            for (int k = 0; k < 8; k++) pre = fmaf(lat[k], Wl[o * 8 + k], pre);
            float lv = tanhf(pre);
            float xv = tanhf(xs * Wx[o]);
            float yv; { float z = ys * Wy[o]; yv = fmaxf(z, 0.f) + log1pf(expf(-fabsf(z))); }
            float rv; { float z = rs * Wr[o]; rv = z > 0.f ? z : expm1f(z); }
            float u = xv + yv + rv + lv;
            in_sh[o * PITCH + s] = expf(-0.5f * u * u);   // gaussian
        }
    }
    __syncthreads();
    // f = sin(f0 @ W1.T + b1)
    gemm64(in_sh, w_sh, b1, 3, f_sh, s, og);

    // ---- graph nodes ----
    for (int j = 0; j < NN; j++) {
        __syncthreads();                 // prev GEMM done (w_sh free, hs[j-1] valid)
        stage_w(gW + j * 4096, w_sh, t);
        const float* src = f_sh;         // sources take f
        unsigned pm = gd.pm[j];
        if (pm) {
            for (int e = t; e < 2048; e += NTHREADS) {
                int off = (e >> 5) * PITCH + (e & 31);
                float v = 0.f;
#pragma unroll
                for (int i = 0; i < NN; i++)
                    if ((pm >> i) & 1) v += hs[i * BUF_F + off];
                in_sh[off] = v;
            }
            src = in_sh;
        }
        __syncthreads();
        gemm64(src, w_sh, gB + j * 64, j % 5, hs + j * BUF_F, s, og);
    }

    // ---- aggregate sinks ----
    __syncthreads();
    {
        unsigned sk = gd.sink_mask;
        for (int e = t; e < 2048; e += NTHREADS) {
            int off = (e >> 5) * PITCH + (e & 31);
            float v = 0.f;
#pragma unroll
            for (int i = 0; i < NN; i++)
                if ((sk >> i) & 1) v += hs[i * BUF_F + off];
            in_sh[off] = v;
        }
    }
    __syncthreads();

    // ---- output head: sigmoid((agg @ outW.T + outb) * scale) ----
    if (og < 3) {
        float acc = outb[og];
        const float* wr = outW + og * 64;
        const float* ip = in_sh + s;
#pragma unroll 8
        for (int k = 0; k < 64; k++) acc = fmaf(ip[k * PITCH], wr[k], acc);
        acc *= scale[0];
        out[gs * 3 + og] = 1.f / (1.f + expf(-acc));
    }
}

// ---------------- host: replicate np.random.RandomState(0) graph ----------------

namespace {

struct MT19937 {
    uint32_t mt[624];
    int mti;
    void seed(uint32_t s) {
        mt[0] = s;
        for (int i = 1; i < 624; i++)
            mt[i] = 1812433253u * (mt[i - 1] ^ (mt[i - 1] >> 30)) + (uint32_t)i;
        mti = 624;
    }
    uint32_t next32() {
        if (mti >= 624) {
            for (int i = 0; i < 624; i++) {
                uint32_t y = (mt[i] & 0x80000000u) | (mt[(i + 1) % 624] & 0x7fffffffu);
                uint32_t v = mt[(i + 397) % 624] ^ (y >> 1);
                if (y & 1u) v ^= 0x9908b0dfu;
                mt[i] = v;
            }
            mti = 0;
        }
        uint32_t y = mt[mti++];
        y ^= y >> 11;
        y ^= (y << 7)  & 0x9d2c5680u;
        y ^= (y << 15) & 0xefc60000u;
        y ^= y >> 18;
        return y;
    }
    double rnd() {  // numpy legacy rk_double
        uint32_t a = next32() >> 5, b = next32() >> 6;
        return (a * 67108864.0 + b) / 9007199254740992.0;
    }
    uint32_t randint(uint32_t n) {  // numpy legacy masked-rejection, 32-bit path
        uint32_t rng = n - 1;
        if (rng == 0) return 0;     // no draw consumed
        uint32_t mask = rng;
        mask |= mask >> 1; mask |= mask >> 2; mask |= mask >> 4;
        mask |= mask >> 8; mask |= mask >> 16;
        uint32_t v;
        do { v = next32() & mask; } while (v > rng);
        return v;
    }
};

void build_graph_host(GraphDesc& gd) {
    MT19937 rng; rng.seed(0u);
    const int n = NN;
    bool adj[NN][NN] = {};
    for (int i = 0; i < n; i++) {
        for (int d = 1; d <= 2; d++) {          // k=4 -> d in {1,2}
            int j = (i + d) % n;
            if (rng.rnd() < 0.75) j = (int)rng.randint((uint32_t)n);
            int a = i < j ? i : j, b = i < j ? j : i;
            if (a != b) adj[a][b] = true;
        }
    }
    unsigned pm[NN] = {};
    for (int a = 0; a < n; a++)
        for (int b = 0; b < n; b++)
            if (adj[a][b]) pm[b] |= 1u << a;
    for (int j = 1; j < n; j++) {
        if (!pm[j]) {
            uint32_t a = rng.randint((uint32_t)j);
            adj[a][j] = true;
            pm[j] |= 1u << a;
        }
    }
    unsigned sinks = 0;
    for (int j = 0; j < n; j++) {
        bool has_succ = false;
        for (int b = 0; b < n; b++) if (adj[j][b]) has_succ = true;
        if (!has_succ) sinks |= 1u << j;
    }
    for (int j = 0; j < n; j++) gd.pm[j] = pm[j];
    gd.sink_mask = sinks;
}

}  // namespace

// ---------------- launch ----------------

extern "C" void kernel_launch(void* const* d_in, const int* in_sizes, int n_in,
                              void* d_out, int out_size) {
    (void)n_in; (void)out_size;
    GraphDesc gd;
    build_graph_host(gd);

    const int B = in_sizes[0] / 3;      // inputs is (B, 3, 1)
    const int ntiles = B / TILE;

    const size_t smem = (size_t)(4096 + 2 * BUF_F + NN * BUF_F) * sizeof(float); // 168448 B
    cudaFuncSetAttribute(inr_kernel, cudaFuncAttributeMaxDynamicSharedMemorySize, (int)smem);

    inr_kernel<<<ntiles, NTHREADS, smem>>>(
        (const float*)d_in[0],  (const float*)d_in[1],  (const float*)d_in[2],
        (const float*)d_in[3],  (const float*)d_in[4],  (const float*)d_in[5],
        (const float*)d_in[6],  (const float*)d_in[7],  (const float*)d_in[8],
        (const float*)d_in[9],  (const float*)d_in[10], (const float*)d_in[11],
        (const float*)d_in[12], (const float*)d_in[13], (float*)d_out, gd);
}

// round 2
// speedup vs baseline: 1.3516x; 1.3516x over previous
#include <cuda_runtime.h>
#include <cstdint>

#define NN 16
#define WD 64
#define PITCH 36                 // floats per row (16B-aligned rows for LDS.128)
#define TILE 32
#define NT 256
#define BUF (WD * PITCH)         // 2304 floats / 9216 B per [64][36] buffer
#define NSTEP 17                 // W1 layer + 16 graph nodes

struct Plan {
    int nslot;
    int srcSlot[NSTEP];          // slot gemm reads; -1 => tmp (multi-pred sum)
    int outSlot[NSTEP];          // -1 => sink: accumulate into agg
    int nPreds[NSTEP];           // >1 only for multi-pred (sum pass)
    int act[NSTEP];
    unsigned char predSlot[NSTEP][NN];
};

// ---------------- device helpers ----------------

__device__ __forceinline__ unsigned long long pk2(float x) {
    unsigned long long r; unsigned xi = __float_as_uint(x);
    asm("mov.b64 %0, {%1, %1};" : "=l"(r) : "r"(xi));
    return r;
}
__device__ __forceinline__ void upk2(unsigned long long v, float& lo, float& hi) {
    unsigned a, b;
    asm("mov.b64 {%0, %1}, %2;" : "=r"(a), "=r"(b) : "l"(v));
    lo = __uint_as_float(a); hi = __uint_as_float(b);
}
__device__ __forceinline__ void ffma2(unsigned long long& acc,
                                      unsigned long long a, unsigned long long b) {
    asm("fma.rn.f32x2 %0, %1, %2, %0;" : "+l"(acc) : "l"(a), "l"(b));
}

// GRAPH_ACTS = [tanh, elu, softplus, sin, gaussian]
__device__ __forceinline__ float actf(int id, float v) {
    switch (id) {
        case 0:  return tanhf(v);
        case 1:  return v > 0.f ? v : expm1f(v);
        case 2:  return fmaxf(v, 0.f) + log1pf(expf(-fabsf(v)));
        case 3:  return sinf(v);
        default: return expf(-0.5f * v * v);
    }
}

// prefetch a 64x64 row-major weight matrix slice into 4 float4 regs
__device__ __forceinline__ void ldg_w(const float* __restrict__ gw, float4* wp, int t) {
    const float4* src = (const float4*)(gw + (t >> 2) * 64 + (t & 3) * 16);
#pragma unroll
    for (int q = 0; q < 4; q++) wp[q] = src[q];
}
// store prefetched regs transposed into shared: wsh[k*64 + o]
__device__ __forceinline__ void sts_w(const float4* wp, float* __restrict__ wsh, int t) {
    int o  = t >> 2;
    int kb = (t & 3) << 4;
#pragma unroll
    for (int q = 0; q < 4; q++) {
        int k = kb + q * 4;
        wsh[(k + 0) * 64 + o] = wp[q].x;
        wsh[(k + 1) * 64 + o] = wp[q].y;
        wsh[(k + 2) * 64 + o] = wp[q].z;
        wsh[(k + 3) * 64 + o] = wp[q].w;
    }
}

// GEMM: out[o][s] = act( sum_k in[k? no: in[s][k]] ... ) with column-major [64][PITCH]
// thread = (sq, ot): samples sq*4..+3, outputs ot*2, ot*2+1. Sample-packed f32x2.
__device__ __forceinline__ void gemm64(const float* __restrict__ in,
                                       const float* __restrict__ wsh,
                                       const float* __restrict__ bias_g,
                                       int actId, float* __restrict__ outp,
                                       bool accum, int sq, int ot) {
    float2 bv = *(const float2*)(bias_g + ot * 2);   // hidden behind the k-loop
    unsigned long long a00 = 0, a01 = 0, a10 = 0, a11 = 0;
    const float* ap = in + sq * 4;
    const float* wp = wsh + ot * 2;
#pragma unroll 16
    for (int k = 0; k < 64; k++) {
        ulonglong2 av = *(const ulonglong2*)(ap + k * PITCH);   // 4 activations (2 f32x2)
        float2 wv = *(const float2*)(wp + k * 64);              // 2 weight scalars
        unsigned long long w0 = pk2(wv.x), w1 = pk2(wv.y);
        ffma2(a00, av.x, w0); ffma2(a01, av.y, w0);
        ffma2(a10, av.x, w1); ffma2(a11, av.y, w1);
    }
    float r0, r1, r2, r3, q0, q1, q2, q3;
    upk2(a00, r0, r1); upk2(a01, r2, r3);
    upk2(a10, q0, q1); upk2(a11, q2, q3);
    float4 o0, o1;
    o0.x = actf(actId, r0 + bv.x); o0.y = actf(actId, r1 + bv.x);
    o0.z = actf(actId, r2 + bv.x); o0.w = actf(actId, r3 + bv.x);
    o1.x = actf(actId, q0 + bv.y); o1.y = actf(actId, q1 + bv.y);
    o1.z = actf(actId, q2 + bv.y); o1.w = actf(actId, q3 + bv.y);
    float* p0 = outp + (ot * 2) * PITCH + sq * 4;
    float* p1 = p0 + PITCH;
    if (accum) {
        float4 c0 = *(const float4*)p0, c1 = *(const float4*)p1;
        o0.x += c0.x; o0.y += c0.y; o0.z += c0.z; o0.w += c0.w;
        o1.x += c1.x; o1.y += c1.y; o1.z += c1.z; o1.w += c1.w;
    }
    *(float4*)p0 = o0; *(float4*)p1 = o1;
}

// ---------------- kernel ----------------

__global__ void __launch_bounds__(NT, 2)
inr_kernel(const float* __restrict__ inp, const float* __restrict__ lats,
           const float* __restrict__ Wl, const float* __restrict__ bl,
           const float* __restrict__ Wx, const float* __restrict__ Wy,
           const float* __restrict__ Wr, const float* __restrict__ W1,
           const float* __restrict__ b1, const float* __restrict__ gW,
           const float* __restrict__ gB, const float* __restrict__ outW,
           const float* __restrict__ outb, const float* __restrict__ scale,
           float* __restrict__ out, Plan pl, int encSlot) {
    extern __shared__ float sm[];
    float* w_sh = sm;            // 4096 floats
    float* tmp  = sm + 4096;     // BUF (multi-pred sums)
    float* agg  = tmp + BUF;     // BUF (sink accumulator)
    float* bufs = agg + BUF;     // nslot * BUF

    const int t  = threadIdx.x;
    const int sq = t & 7;        // sample quad (8 quads = 32 samples)
    const int ot = t >> 3;       // output pair (32 pairs = 64 outputs)
    const int s  = t & 31;
    const int og = t >> 5;
    const int gs = blockIdx.x * TILE + s;

    // prefetch W1 into regs
    float4 wpf[4];
    ldg_w(W1, wpf, t);

    // encode -> bufs[encSlot]
    {
        float* enc = bufs + encSlot * BUF;
        float xs = inp[gs * 3 + 0], ys = inp[gs * 3 + 1], rs = inp[gs * 3 + 2];
        float lat[8];
        const float4* lp = (const float4*)(lats + gs * 8);
        float4 l0 = lp[0], l1 = lp[1];
        lat[0] = l0.x; lat[1] = l0.y; lat[2] = l0.z; lat[3] = l0.w;
        lat[4] = l1.x; lat[5] = l1.y; lat[6] = l1.z; lat[7] = l1.w;
#pragma unroll
        for (int i = 0; i < 8; i++) {
            int o = og * 8 + i;
            float pre = bl[o];
#pragma unroll
            for (int k = 0; k < 8; k++) pre = fmaf(lat[k], Wl[o * 8 + k], pre);
            float lv = tanhf(pre);
            float xv = tanhf(xs * Wx[o]);
            float yv; { float z = ys * Wy[o]; yv = fmaxf(z, 0.f) + log1pf(expf(-fabsf(z))); }
            float rv; { float z = rs * Wr[o]; rv = z > 0.f ? z : expm1f(z); }
            float u = xv + yv + rv + lv;
            enc[o * PITCH + s] = expf(-0.5f * u * u);
        }
    }
    // zero agg (active 64x32 region)
    {
        float4 z = make_float4(0.f, 0.f, 0.f, 0.f);
#pragma unroll
        for (int q = t; q < 512; q += NT)
            *(float4*)(agg + (q >> 3) * PITCH + (q & 7) * 4) = z;
    }

    // ---- 17 GEMM steps ----
    for (int st = 0; st < NSTEP; st++) {
        __syncthreads();                       // prior gemm done: w_sh reusable
        sts_w(wpf, w_sh, t);
        if (st < NSTEP - 1) ldg_w(gW + st * 4096, wpf, t);   // step st+1 weights

        const float* src;
        int ss = pl.srcSlot[st];
        if (ss < 0) {                          // multi-pred: sum into tmp
            int np = pl.nPreds[st];
            const float* p0 = bufs + pl.predSlot[st][0] * BUF;
#pragma unroll 2
            for (int q = t; q < 512; q += NT) {
                int off = (q >> 3) * PITCH + (q & 7) * 4;
                float4 v = *(const float4*)(p0 + off);
                for (int p = 1; p < np; p++) {
                    float4 u = *(const float4*)(bufs + pl.predSlot[st][p] * BUF + off);
                    v.x += u.x; v.y += u.y; v.z += u.z; v.w += u.w;
                }
                *(float4*)(tmp + off) = v;
            }
            src = tmp;
        } else {
            src = bufs + ss * BUF;
        }
        __syncthreads();                       // weights + src visible

        int os = pl.outSlot[st];
        const float* bias = (st == 0) ? b1 : gB + (st - 1) * 64;
        gemm64(src, w_sh, bias, pl.act[st],
               (os < 0) ? agg : bufs + os * BUF, os < 0, sq, ot);
    }
    __syncthreads();

    // ---- head: sigmoid((agg @ outW.T + outb) * scale) ----
    if (og < 3) {
        float acc = outb[og];
        const float* wr = outW + og * 64;
        const float* ip = agg + s;
#pragma unroll 8
        for (int k = 0; k < 64; k++) acc = fmaf(ip[k * PITCH], wr[k], acc);
        acc *= scale[0];
        out[gs * 3 + og] = 1.f / (1.f + expf(-acc));
    }
}

// ---------------- host: replicate np.random.RandomState(0) graph + slot plan ----------------

namespace {

struct MT19937 {
    uint32_t mt[624];
    int mti;
    void seed(uint32_t s) {
        mt[0] = s;
        for (int i = 1; i < 624; i++)
            mt[i] = 1812433253u * (mt[i - 1] ^ (mt[i - 1] >> 30)) + (uint32_t)i;
        mti = 624;
    }
    uint32_t next32() {
        if (mti >= 624) {
            for (int i = 0; i < 624; i++) {
                uint32_t y = (mt[i] & 0x80000000u) | (mt[(i + 1) % 624] & 0x7fffffffu);
                uint32_t v = mt[(i + 397) % 624] ^ (y >> 1);
                if (y & 1u) v ^= 0x9908b0dfu;
                mt[i] = v;
            }
            mti = 0;
        }
        uint32_t y = mt[mti++];
        y ^= y >> 11;
        y ^= (y << 7)  & 0x9d2c5680u;
        y ^= (y << 15) & 0xefc60000u;
        y ^= y >> 18;
        return y;
    }
    double rnd() {
        uint32_t a = next32() >> 5, b = next32() >> 6;
        return (a * 67108864.0 + b) / 9007199254740992.0;
    }
    uint32_t randint(uint32_t n) {
        uint32_t rng = n - 1;
        if (rng == 0) return 0;
        uint32_t mask = rng;
        mask |= mask >> 1; mask |= mask >> 2; mask |= mask >> 4;
        mask |= mask >> 8; mask |= mask >> 16;
        uint32_t v;
        do { v = next32() & mask; } while (v > rng);
        return v;
    }
};

struct HostPlan { Plan pl; int encSlot; };

void build_plan(HostPlan& hp) {
    // ---- graph (matches reference build_graph, seed 0) ----
    MT19937 rng; rng.seed(0u);
    const int n = NN;
    bool adj[NN][NN] = {};
    for (int i = 0; i < n; i++) {
        for (int d = 1; d <= 2; d++) {
            int j = (i + d) % n;
            if (rng.rnd() < 0.75) j = (int)rng.randint((uint32_t)n);
            int a = i < j ? i : j, b = i < j ? j : i;
            if (a != b) adj[a][b] = true;
        }
    }
    unsigned pm[NN] = {};
    for (int a = 0; a < n; a++)
        for (int b = 0; b < n; b++)
            if (adj[a][b]) pm[b] |= 1u << a;
    for (int j = 1; j < n; j++) {
        if (!pm[j]) {
            uint32_t a = rng.randint((uint32_t)j);
            adj[a][j] = true;
            pm[j] |= 1u << a;
        }
    }
    bool isSink[NN];
    for (int j = 0; j < n; j++) {
        bool has_succ = false;
        for (int b = 0; b < n; b++) if (adj[j][b]) has_succ = true;
        isSink[j] = !has_succ;
    }

    // ---- liveness-based slot assignment ----
    // value ids: 0..15 = node outputs, 16 = f, 17 = enc
    int uses[18] = {0};
    uses[17] = 1;
    for (int j = 0; j < n; j++) {
        if (pm[j] == 0) uses[16]++;
        else for (int i = 0; i < n; i++) if ((pm[j] >> i) & 1) uses[i]++;
    }
    int freeS[20], nFree = 0, ns = 0;
    auto alloc = [&]() { return nFree ? freeS[--nFree] : ns++; };
    auto release = [&](int sl) { freeS[nFree++] = sl; };
    int slotOf[18];

    Plan& P = hp.pl;
    slotOf[17] = alloc();
    hp.encSlot = slotOf[17];
    // step 0: f = sin(enc @ W1.T + b1)
    P.srcSlot[0] = slotOf[17]; P.nPreds[0] = 0; P.act[0] = 3;
    slotOf[16] = alloc();
    P.outSlot[0] = slotOf[16];
    if (--uses[17] == 0) release(slotOf[17]);

    for (int j = 0; j < n; j++) {
        int st = j + 1;
        P.act[st] = j % 5;
        int np = 0;
        for (int i = 0; i < n; i++) if ((pm[j] >> i) & 1) np++;
        if (np == 0) {
            P.srcSlot[st] = slotOf[16]; P.nPreds[st] = 0;
        } else if (np == 1) {
            int p = 0; while (!((pm[j] >> p) & 1)) p++;
            P.srcSlot[st] = slotOf[p]; P.nPreds[st] = 0;
        } else {
            P.srcSlot[st] = -1; P.nPreds[st] = np;
            int c = 0;
            for (int i = 0; i < n; i++)
                if ((pm[j] >> i) & 1) P.predSlot[st][c++] = (unsigned char)slotOf[i];
            // preds fully consumed by the sum pass before the gemm writes
            for (int i = 0; i < n; i++)
                if ((pm[j] >> i) & 1) { if (--uses[i] == 0) release(slotOf[i]); }
        }
        if (isSink[j]) {
            P.outSlot[st] = -1;
        } else {
            slotOf[j] = alloc();
            P.outSlot[st] = slotOf[j];
        }
        if (np == 1) {
            int p = 0; while (!((pm[j] >> p) & 1)) p++;
            if (--uses[p] == 0) release(slotOf[p]);
        }
        if (np == 0) { if (--uses[16] == 0) release(slotOf[16]); }
    }
    P.nslot = ns;
}

}  // namespace

// ---------------- launch ----------------

extern "C" void kernel_launch(void* const* d_in, const int* in_sizes, int n_in,
                              void* d_out, int out_size) {
    (void)n_in; (void)out_size;
    HostPlan hp;
    build_plan(hp);

    const int B = in_sizes[0] / 3;
    const int ntiles = B / TILE;

    const size_t smem = (size_t)(4096 + (2 + hp.pl.nslot) * BUF) * sizeof(float);
    cudaFuncSetAttribute(inr_kernel, cudaFuncAttributeMaxDynamicSharedMemorySize,
                         (int)smem);

    inr_kernel<<<ntiles, NT, smem>>>(
        (const float*)d_in[0],  (const float*)d_in[1],  (const float*)d_in[2],
        (const float*)d_in[3],  (const float*)d_in[4],  (const float*)d_in[5],
        (const float*)d_in[6],  (const float*)d_in[7],  (const float*)d_in[8],
        (const float*)d_in[9],  (const float*)d_in[10], (const float*)d_in[11],
        (const float*)d_in[12], (const float*)d_in[13], (float*)d_out,
        hp.pl, hp.encSlot);
}

// round 3
// speedup vs baseline: 1.8464x; 1.3661x over previous
#include <cuda_runtime.h>
#include <cstdint>

#define NN 16
#define WD 64
#define PITCH 36                 // floats per buffer row (16B-aligned, conflict-free)
#define TILE 32
#define NT 128
#define BUF (WD * PITCH)         // 2304 floats / 9216 B
#define NSTEP 17

struct Plan {
    int nslot;
    int encSlot, aggSlot;
    int srcSlot[NSTEP];          // >=0: read slot; -1: use sum
    int sumSlot[NSTEP];
    int outSlot[NSTEP];
    int accum[NSTEP];            // 1: add into outSlot (sink aggregation)
    int act[NSTEP];
    int nPreds[NSTEP];
    unsigned char predSlot[NSTEP][NN];
};

// ---------------- device helpers ----------------

__device__ __forceinline__ unsigned long long pk2(float x) {
    unsigned long long r; unsigned xi = __float_as_uint(x);
    asm("mov.b64 %0, {%1, %1};" : "=l"(r) : "r"(xi));
    return r;
}
__device__ __forceinline__ void upk2(unsigned long long v, float& lo, float& hi) {
    unsigned a, b;
    asm("mov.b64 {%0, %1}, %2;" : "=r"(a), "=r"(b) : "l"(v));
    lo = __uint_as_float(a); hi = __uint_as_float(b);
}
__device__ __forceinline__ void ffma2(unsigned long long& acc,
                                      unsigned long long a, unsigned long long b) {
    asm("fma.rn.f32x2 %0, %1, %2, %0;" : "+l"(acc) : "l"(a), "l"(b));
}

// GRAPH_ACTS = [tanh, elu, softplus, sin, gaussian] — fast intrinsic forms
__device__ __forceinline__ float actf(int id, float v) {
    switch (id) {
        case 0:  return tanhf(v);
        case 1:  return v > 0.f ? v : (__expf(v) - 1.f);
        case 2:  return fmaxf(v, 0.f) + __logf(1.f + __expf(-fabsf(v)));
        case 3:  return __sinf(v);
        default: return __expf(-0.5f * v * v);
    }
}

// prefetch full 64x64 weight matrix: thread t loads row o=t&63, half kh=t>>6 (128B)
__device__ __forceinline__ void ldg_w(const float* __restrict__ gw, float4* wp, int t) {
    const float4* src = (const float4*)(gw + (t & 63) * 64 + (t >> 6) * 32);
#pragma unroll
    for (int q = 0; q < 8; q++) wp[q] = src[q];
}
// store transposed into shared: wsh[k*64 + o] (conflict-free: warp lanes span o)
__device__ __forceinline__ void sts_w(const float4* wp, float* __restrict__ wsh, int t) {
    int o  = t & 63;
    int kb = (t >> 6) * 32;
#pragma unroll
    for (int q = 0; q < 8; q++) {
        int k = kb + q * 4;
        wsh[(k + 0) * 64 + o] = wp[q].x;
        wsh[(k + 1) * 64 + o] = wp[q].y;
        wsh[(k + 2) * 64 + o] = wp[q].z;
        wsh[(k + 3) * 64 + o] = wp[q].w;
    }
}

// GEMM: thread (sq 0..7, oq 0..15) computes samples sq*4..+3 x outputs oq*4..+3
__device__ __forceinline__ void gemm64(const float* __restrict__ in,
                                       const float* __restrict__ wsh,
                                       const float* __restrict__ bias_g,
                                       int actId, float* __restrict__ outp,
                                       bool accum, int sq, int oq) {
    unsigned long long acc[4][2];
#pragma unroll
    for (int i = 0; i < 4; i++) acc[i][0] = acc[i][1] = 0;

    const float* ap = in + sq * 4;
    const float* wp = wsh + oq * 4;
#pragma unroll 16
    for (int k = 0; k < 64; k++) {
        ulonglong2 av = *(const ulonglong2*)(ap + k * PITCH);   // 4 activations
        float4 wv = *(const float4*)(wp + k * 64);              // 4 weights
        unsigned long long w0 = pk2(wv.x), w1 = pk2(wv.y);
        unsigned long long w2 = pk2(wv.z), w3 = pk2(wv.w);
        ffma2(acc[0][0], av.x, w0); ffma2(acc[0][1], av.y, w0);
        ffma2(acc[1][0], av.x, w1); ffma2(acc[1][1], av.y, w1);
        ffma2(acc[2][0], av.x, w2); ffma2(acc[2][1], av.y, w2);
        ffma2(acc[3][0], av.x, w3); ffma2(acc[3][1], av.y, w3);
    }
    float4 bv = *(const float4*)(bias_g + oq * 4);
    float bb[4] = {bv.x, bv.y, bv.z, bv.w};
#pragma unroll
    for (int i = 0; i < 4; i++) {
        float r0, r1, r2, r3;
        upk2(acc[i][0], r0, r1); upk2(acc[i][1], r2, r3);
        float4 o4;
        o4.x = actf(actId, r0 + bb[i]); o4.y = actf(actId, r1 + bb[i]);
        o4.z = actf(actId, r2 + bb[i]); o4.w = actf(actId, r3 + bb[i]);
        float* p = outp + (oq * 4 + i) * PITCH + sq * 4;
        if (accum) {
            float4 c = *(const float4*)p;
            o4.x += c.x; o4.y += c.y; o4.z += c.z; o4.w += c.w;
        }
        *(float4*)p = o4;
    }
}

// ---------------- kernel ----------------

__global__ void __launch_bounds__(NT, 2)
inr_kernel(const float* __restrict__ inp, const float* __restrict__ lats,
           const float* __restrict__ Wl, const float* __restrict__ bl,
           const float* __restrict__ Wx, const float* __restrict__ Wy,
           const float* __restrict__ Wr, const float* __restrict__ W1,
           const float* __restrict__ b1, const float* __restrict__ gW,
           const float* __restrict__ gB, const float* __restrict__ outW,
           const float* __restrict__ outb, const float* __restrict__ scale,
           float* __restrict__ out, Plan pl) {
    extern __shared__ float sm[];
    float* w_sh = sm;            // 4096 floats (16 KB)
    float* bufs = sm + 4096;     // nslot * BUF

    const int t  = threadIdx.x;
    const int sq = t & 7;
    const int oq = t >> 3;
    const int s  = t & 31;
    const int og = t >> 5;       // 0..3
    const int gsb = blockIdx.x * TILE;

    float4 wpf[8];
    ldg_w(W1, wpf, t);

    // ---- encode -> bufs[encSlot]: thread (s, og) does 16 outputs for sample s ----
    {
        float* enc = bufs + pl.encSlot * BUF;
        int gs = gsb + s;
        float xs = inp[gs * 3 + 0], ys = inp[gs * 3 + 1], rs = inp[gs * 3 + 2];
        float lat[8];
        const float4* lp = (const float4*)(lats + gs * 8);
        float4 l0 = lp[0], l1 = lp[1];
        lat[0] = l0.x; lat[1] = l0.y; lat[2] = l0.z; lat[3] = l0.w;
        lat[4] = l1.x; lat[5] = l1.y; lat[6] = l1.z; lat[7] = l1.w;
#pragma unroll
        for (int i = 0; i < 16; i++) {
            int o = og * 16 + i;
            float pre = bl[o];
#pragma unroll
            for (int k = 0; k < 8; k++) pre = fmaf(lat[k], Wl[o * 8 + k], pre);
            float lv = tanhf(pre);
            float xv = tanhf(xs * Wx[o]);
            float yv; { float z = ys * Wy[o]; yv = fmaxf(z, 0.f) + __logf(1.f + __expf(-fabsf(z))); }
            float rv; { float z = rs * Wr[o]; rv = z > 0.f ? z : (__expf(z) - 1.f); }
            float u = xv + yv + rv + lv;
            enc[o * PITCH + s] = __expf(-0.5f * u * u);
        }
    }

    // ---- 17 GEMM steps ----
    for (int st = 0; st < NSTEP; st++) {
        __syncthreads();                         // prev gemm done; outputs visible
        sts_w(wpf, w_sh, t);
        if (st < NSTEP - 1) ldg_w(gW + st * 4096, wpf, t);

        int ss = pl.srcSlot[st];
        if (ss < 0) {                            // multi-pred sum -> sumSlot
            int np = pl.nPreds[st];
            const float* p0 = bufs + pl.predSlot[st][0] * BUF;
            float* dst = bufs + pl.sumSlot[st] * BUF;
#pragma unroll 4
            for (int q = t; q < 512; q += NT) {
                int off = (q >> 3) * PITCH + (q & 7) * 4;
                float4 v = *(const float4*)(p0 + off);
                for (int p = 1; p < np; p++) {
                    float4 u = *(const float4*)(bufs + pl.predSlot[st][p] * BUF + off);
                    v.x += u.x; v.y += u.y; v.z += u.z; v.w += u.w;
                }
                *(float4*)(dst + off) = v;
            }
            ss = pl.sumSlot[st];
        }
        __syncthreads();                         // weights + src visible

        const float* bias = (st == 0) ? b1 : gB + (st - 1) * 64;
        gemm64(bufs + ss * BUF, w_sh, bias, pl.act[st],
               bufs + pl.outSlot[st] * BUF, pl.accum[st] != 0, sq, oq);
    }
    __syncthreads();

    // ---- head: sigmoid((agg @ outW.T + outb) * scale) ----
    if (og < 3) {
        float acc = outb[og];
        const float* wr = outW + og * 64;
        const float* ip = bufs + pl.aggSlot * BUF + s;
#pragma unroll 8
        for (int k = 0; k < 64; k++) acc = fmaf(ip[k * PITCH], wr[k], acc);
        acc *= scale[0];
        out[(gsb + s) * 3 + og] = 1.f / (1.f + __expf(-acc));
    }
}

// ---------------- host: graph replication + slot plan ----------------

namespace {

struct MT19937 {
    uint32_t mt[624];
    int mti;
    void seed(uint32_t s) {
        mt[0] = s;
        for (int i = 1; i < 624; i++)
            mt[i] = 1812433253u * (mt[i - 1] ^ (mt[i - 1] >> 30)) + (uint32_t)i;
        mti = 624;
    }
    uint32_t next32() {
        if (mti >= 624) {
            for (int i = 0; i < 624; i++) {
                uint32_t y = (mt[i] & 0x80000000u) | (mt[(i + 1) % 624] & 0x7fffffffu);
                uint32_t v = mt[(i + 397) % 624] ^ (y >> 1);
                if (y & 1u) v ^= 0x9908b0dfu;
                mt[i] = v;
            }
            mti = 0;
        }
        uint32_t y = mt[mti++];
        y ^= y >> 11;
        y ^= (y << 7)  & 0x9d2c5680u;
        y ^= (y << 15) & 0xefc60000u;
        y ^= y >> 18;
        return y;
    }
    double rnd() {
        uint32_t a = next32() >> 5, b = next32() >> 6;
        return (a * 67108864.0 + b) / 9007199254740992.0;
    }
    uint32_t randint(uint32_t n) {
        uint32_t rng = n - 1;
        if (rng == 0) return 0;
        uint32_t mask = rng;
        mask |= mask >> 1; mask |= mask >> 2; mask |= mask >> 4;
        mask |= mask >> 8; mask |= mask >> 16;
        uint32_t v;
        do { v = next32() & mask; } while (v > rng);
        return v;
    }
};

void build_plan(Plan& P) {
    // ---- graph (matches reference build_graph, seed 0) ----
    MT19937 rng; rng.seed(0u);
    const int n = NN;
    bool adj[NN][NN] = {};
    for (int i = 0; i < n; i++) {
        for (int d = 1; d <= 2; d++) {
            int j = (i + d) % n;
            if (rng.rnd() < 0.75) j = (int)rng.randint((uint32_t)n);
            int a = i < j ? i : j, b = i < j ? j : i;
            if (a != b) adj[a][b] = true;
        }
    }
    unsigned pm[NN] = {};
    for (int a = 0; a < n; a++)
        for (int b = 0; b < n; b++)
            if (adj[a][b]) pm[b] |= 1u << a;
    for (int j = 1; j < n; j++) {
        if (!pm[j]) {
            uint32_t a = rng.randint((uint32_t)j);
            adj[a][j] = true;
            pm[j] |= 1u << a;
        }
    }
    bool isSink[NN];
    for (int j = 0; j < n; j++) {
        bool has_succ = false;
        for (int b = 0; b < n; b++) if (adj[j][b]) has_succ = true;
        isSink[j] = !has_succ;
    }

    // ---- liveness slot allocation: values 0..15 nodes, 16 f, 17 enc ----
    int uses[18] = {0};
    uses[17] = 1;
    for (int j = 0; j < n; j++) {
        if (pm[j] == 0) uses[16]++;
        else for (int i = 0; i < n; i++) if ((pm[j] >> i) & 1) uses[i]++;
    }
    int freeS[24], nFree = 0, ns = 0;
    auto alloc = [&]() { return nFree ? freeS[--nFree] : ns++; };
    auto release = [&](int sl) { freeS[nFree++] = sl; };
    int slotOf[18];

    P.aggSlot = -1;
    slotOf[17] = alloc();
    P.encSlot = slotOf[17];

    // step 0: f = sin(enc @ W1.T + b1)
    P.srcSlot[0] = slotOf[17]; P.sumSlot[0] = -1; P.nPreds[0] = 0;
    P.act[0] = 3; P.accum[0] = 0;
    slotOf[16] = alloc();                 // out ≠ src (src still allocated)
    P.outSlot[0] = slotOf[16];
    if (--uses[17] == 0) release(slotOf[17]);

    for (int j = 0; j < n; j++) {
        int st = j + 1;
        P.act[st] = j % 5;
        P.sumSlot[st] = -1; P.nPreds[st] = 0;
        int np = 0;
        for (int i = 0; i < n; i++) if ((pm[j] >> i) & 1) np++;

        int srcVal = -1;
        if (np == 0) {
            srcVal = 16;
            P.srcSlot[st] = slotOf[16];
        } else if (np == 1) {
            int p = 0; while (!((pm[j] >> p) & 1)) p++;
            srcVal = p;
            P.srcSlot[st] = slotOf[p];
        } else {
            P.srcSlot[st] = -1; P.nPreds[st] = np;
            int c = 0;
            for (int i = 0; i < n; i++)
                if ((pm[j] >> i) & 1) P.predSlot[st][c++] = (unsigned char)slotOf[i];
            // preds fully consumed by the elementwise sum pass
            for (int i = 0; i < n; i++)
                if ((pm[j] >> i) & 1) { if (--uses[i] == 0) release(slotOf[i]); }
            P.sumSlot[st] = alloc();      // may safely reuse a dead pred slot
        }

        // output slot (allocated while src/sum still held -> no aliasing)
        if (isSink[j]) {
            if (P.aggSlot < 0) { P.aggSlot = alloc(); P.accum[st] = 0; }
            else P.accum[st] = 1;
            P.outSlot[st] = P.aggSlot;
        } else {
            P.accum[st] = 0;
            slotOf[j] = alloc();
            P.outSlot[st] = slotOf[j];
        }

        // release consumed source after the gemm
        if (np > 1) release(P.sumSlot[st]);
        else if (--uses[srcVal] == 0) release(slotOf[srcVal]);
    }
    P.nslot = ns;
}

}  // namespace

// ---------------- launch ----------------

extern "C" void kernel_launch(void* const* d_in, const int* in_sizes, int n_in,
                              void* d_out, int out_size) {
    (void)n_in; (void)out_size;
    Plan pl;
    build_plan(pl);

    const int B = in_sizes[0] / 3;
    const int ntiles = B / TILE;

    const size_t smem = (size_t)(4096 + pl.nslot * BUF) * sizeof(float);
    cudaFuncSetAttribute(inr_kernel, cudaFuncAttributeMaxDynamicSharedMemorySize,
                         (int)smem);

    inr_kernel<<<ntiles, NT, smem>>>(
        (const float*)d_in[0],  (const float*)d_in[1],  (const float*)d_in[2],
        (const float*)d_in[3],  (const float*)d_in[4],  (const float*)d_in[5],
        (const float*)d_in[6],  (const float*)d_in[7],  (const float*)d_in[8],
        (const float*)d_in[9],  (const float*)d_in[10], (const float*)d_in[11],
        (const float*)d_in[12], (const float*)d_in[13], (float*)d_out, pl);
}